// round 4
// baseline (speedup 1.0000x reference)
#include <cuda_runtime.h>

#define TSTEPS 2048
#define BSIZE  8192
#define HH     0.01f

__device__ __forceinline__ float ex2f(float x) {
    float y; asm("ex2.approx.ftz.f32 %0, %1;" : "=f"(y) : "f"(x)); return y;
}
__device__ __forceinline__ float rcpf(float x) {
    float y; asm("rcp.approx.ftz.f32 %0, %1;" : "=f"(y) : "f"(x)); return y;
}

struct Consts {
    float a11, a12, a13, a14, a22, a23, a24, a33, a34, a44;
    float bm1, bm2, bm3, bm4, bm0;
    float K1, K2;
};

// One recurrence step. FIRST: i==0 (delta=1, x_hat unchanged). ADDSC: add stage cost.
template<bool FIRST, bool ADDSC>
__device__ __forceinline__ void step(const Consts& c, float w1, float w2,
                                     float& x1, float& x2, float& h1, float& h2,
                                     float& acc)
{
    const float E11 = 1.0f - 2.0f * HH;   // 0.98
    const float C1  = 0.5f * HH * HH;     // +h^2/2 (exact RK4 constant, x1 eq)
    const float C2  = -HH * HH;           // -h^2   (x2 eq)

    // Off-critical-path work, hoisted above the MUFU dependency:
    float dx1 = x1 - h1, dx2 = x2 - h2;
    float kuh = fmaf(c.K2, h2, c.K1 * h1);      // K · x_hat
    float kdx = fmaf(c.K2, dx2, c.K1 * dx1);    // K · (x - x_hat)
    float base1 = fmaf(E11, x1, fmaf(HH, x2, w1 + C1));
    float base2 = fmaf(HH, x1, fmaf(E11, x2, w2 + C2));

    float delta, u, h1n, h2n;
    if (FIRST) {
        delta = 1.0f;
        u = kuh;          // K · x_hat (unchanged at i==0)
        h1n = h1; h2n = h2;
    } else {
        // phi' = -log2(e) * (z^T L z + M z + Mo), balanced tree (~24 cyc)
        float ta = fmaf(c.a12, x2, c.a11 * x1);
        float tb = fmaf(c.a13, h1, fmaf(c.a14, h2, c.bm1));
        float q1 = ta + tb;
        float q2 = fmaf(c.a22, x2, fmaf(c.a23, h1, fmaf(c.a24, h2, c.bm2)));
        float q3 = fmaf(c.a33, h1, fmaf(c.a34, h2, c.bm3));
        float q4 = fmaf(c.a44, h2, c.bm4);
        float pa = x1 * q1;
        float pb = fmaf(x2, q2, c.bm0);
        float pc = fmaf(h1, q3, h2 * q4);
        float phiS = (pa + pb) + pc;
        // sigmoid(phi) = 1 / (1 + 2^phiS)
        float e = ex2f(phiS);
        delta = rcpf(1.0f + e);
        u   = fmaf(delta, kdx, kuh);    // K · x_hat_new
        h1n = fmaf(delta, dx1, h1);
        h2n = fmaf(delta, dx2, h2);
    }

    if (ADDSC) {
        float kx = kuh + kdx;           // K · x  (exact: K·xh + K·(x-xh))
        acc = fmaf(x1, x1, acc);
        acc = fmaf(x2, x2, acc);
        acc = fmaf(kx * kx, 0.1f, acc); // R * u_s^2
        acc = acc + delta;              // LAM * delta, LAM = 1
    }

    x1 = fmaf(HH, u, base1);
    x2 = fmaf(HH, u, base2);
    h1 = h1n; h2 = h2n;
}

__global__ void __launch_bounds__(64, 1) cstr_traj_kernel(
    const float* __restrict__ w,   // (B, 2, T)
    const float* __restrict__ K,   // (1, 2)
    const float* __restrict__ L,   // (4, 4)
    const float* __restrict__ M,   // (1, 4)
    const float* __restrict__ Mo,  // (1, 1)
    float* __restrict__ out)       // (B,)
{
    int b = blockIdx.x * blockDim.x + threadIdx.x;

    const float s = -1.44269504088896340736f; // -log2(e): fold into phi coeffs
    Consts c;
    c.K1 = __ldg(K);  c.K2 = __ldg(K + 1);
    float l[16];
#pragma unroll
    for (int i = 0; i < 16; i++) l[i] = __ldg(L + i);
    c.a11 = s * l[0];           c.a22 = s * l[5];
    c.a33 = s * l[10];          c.a44 = s * l[15];
    c.a12 = s * (l[1] + l[4]);  c.a13 = s * (l[2] + l[8]);
    c.a14 = s * (l[3] + l[12]); c.a23 = s * (l[6] + l[9]);
    c.a24 = s * (l[7] + l[13]); c.a34 = s * (l[11] + l[14]);
    c.bm1 = s * __ldg(M);       c.bm2 = s * __ldg(M + 1);
    c.bm3 = s * __ldg(M + 2);   c.bm4 = s * __ldg(M + 3);
    c.bm0 = s * __ldg(Mo);

    const float4* w0 = (const float4*)(w + (size_t)b * 2 * TSTEPS);
    const float4* w1 = (const float4*)(w + (size_t)b * 2 * TSTEPS + TSTEPS);

    float x1 = 1.0f, x2 = 0.0f, h1 = 1.0f, h2 = 0.0f;
    float J = 0.0f;

    // Group 0: i=0 is the FIRST step (delta = 1, x_hat frozen)
    {
        float4 wa = w0[0], wb = w1[0];
        float acc = 0.0f;
        step<true,  true>(c, wa.x, wb.x, x1, x2, h1, h2, acc);
        step<false, true>(c, wa.y, wb.y, x1, x2, h1, h2, acc);
        step<false, true>(c, wa.z, wb.z, x1, x2, h1, h2, acc);
        step<false, true>(c, wa.w, wb.w, x1, x2, h1, h2, acc);
        J += acc;
    }

#pragma unroll 2
    for (int g = 1; g < TSTEPS / 4 - 1; ++g) {
        float4 wa = w0[g], wb = w1[g];
        float acc = 0.0f;
        step<false, true>(c, wa.x, wb.x, x1, x2, h1, h2, acc);
        step<false, true>(c, wa.y, wb.y, x1, x2, h1, h2, acc);
        step<false, true>(c, wa.z, wb.z, x1, x2, h1, h2, acc);
        step<false, true>(c, wa.w, wb.w, x1, x2, h1, h2, acc);
        J += acc;
    }

    // Last group: final step (i = T-1) updates state but adds no stage cost
    {
        const int g = TSTEPS / 4 - 1;
        float4 wa = w0[g], wb = w1[g];
        float acc = 0.0f;
        step<false, true >(c, wa.x, wb.x, x1, x2, h1, h2, acc);
        step<false, true >(c, wa.y, wb.y, x1, x2, h1, h2, acc);
        step<false, true >(c, wa.z, wb.z, x1, x2, h1, h2, acc);
        step<false, false>(c, wa.w, wb.w, x1, x2, h1, h2, acc);
        J += acc;
    }

    // Terminal cost: x_T^T (10 I) x_T
    J = fmaf(10.0f * x1, x1, J);
    J = fmaf(10.0f * x2, x2, J);

    if (b < BSIZE) out[b] = J;
}

extern "C" void kernel_launch(void* const* d_in, const int* in_sizes, int n_in,
                              void* d_out, int out_size)
{
    const float* w  = (const float*)d_in[0];
    const float* K  = (const float*)d_in[1];
    const float* L  = (const float*)d_in[2];
    const float* M  = (const float*)d_in[3];
    const float* Mo = (const float*)d_in[4];
    float* out = (float*)d_out;

    // 8192 trajectories, 1 thread each. 128 blocks x 64 threads -> one wave
    // on 148 SMs, ~1 warp per SMSP (latency-bound regime by design).
    cstr_traj_kernel<<<BSIZE / 64, 64>>>(w, K, L, M, Mo, out);
}

// round 5
// speedup vs baseline: 2.1116x; 2.1116x over previous
#include <cuda_runtime.h>

#define TSTEPS 2048
#define BSIZE  8192
#define HH     0.01f
#define NG     (TSTEPS / 4)   // 512 groups of 4 steps
#define PD     4              // prefetch distance (groups)

__device__ __forceinline__ float tanh_approx(float x) {
    float y; asm("tanh.approx.f32 %0, %1;" : "=f"(y) : "f"(x)); return y;
}

struct Consts {
    float a11, a12, a13, a14, a22, a23, a24, a33, a34, a44;  // 0.5 * symmetrized L
    float bm1, bm2, bm3, bm4, bm0;                           // 0.5 * M, 0.5 * Mo
    float K1, K2;
};

// One recurrence step. ADDSC: add stage cost.
// sigmoid(phi) = 0.5 + 0.5*tanh(phi/2); the 1/2 is folded into the a/bm coeffs.
// Post-tanh chain is a single FMA per state variable; everything else is
// hoisted above the TANH dependency (issues inside the MUFU shadow).
template<bool ADDSC>
__device__ __forceinline__ void step(const Consts& c, float w1, float w2,
                                     float& x1, float& x2, float& h1, float& h2,
                                     float& acc)
{
    const float E11 = 1.0f - 2.0f * HH;   // 0.98
    const float C1  = 0.5f * HH * HH;     // +h^2/2 (exact collapsed RK4, x1 eq)
    const float C2  = -HH * HH;           // -h^2   (x2 eq)

    // ---- off-critical-path (overlaps phi tree + tanh latency) ----
    float dx1 = x1 - h1, dx2 = x2 - h2;
    float kuh  = fmaf(c.K2, h2, c.K1 * h1);                    // K · x_hat
    float kdxh = fmaf(0.5f * c.K2, dx2, (0.5f * c.K1) * dx1);  // 0.5 * K · dx
    float g  = HH * kdxh;                                      // t-coeff of x update
    float bb = fmaf(HH, kuh, g);                               // HH*(K·xh + 0.5 K·dx)
    float base1 = fmaf(E11, x1, fmaf(HH, x2, w1 + C1));
    float base2 = fmaf(HH,  x1, fmaf(E11, x2, w2 + C2));
    float bx1 = base1 + bb, bx2 = base2 + bb;
    float dh1 = 0.5f * dx1, dh2 = 0.5f * dx2;
    float hm1 = h1 + dh1,   hm2 = h2 + dh2;

    // ---- phi tree (depth ~24 cyc), coefficients pre-scaled by 1/2 ----
    float e1 = fmaf(c.a12, x2, c.a11 * x1);
    float e2 = fmaf(c.a13, h1, fmaf(c.a14, h2, c.bm1));
    float q1 = e1 + e2;
    float q2 = fmaf(c.a22, x2, fmaf(c.a23, h1, fmaf(c.a24, h2, c.bm2)));
    float q3 = fmaf(c.a33, h1, fmaf(c.a34, h2, c.bm3));
    float q4 = fmaf(c.a44, h2, c.bm4);
    float p2  = x2 * q2;
    float p4  = fmaf(h2, q4, c.bm0);
    float p34 = fmaf(h1, q3, p4);
    float p12 = fmaf(x1, q1, p2);
    float phi = p12 + p34;

    float t = tanh_approx(phi);           // single MUFU on the chain

    if (ADDSC) {
        float delta = fmaf(0.5f, t, 0.5f);
        float kx = fmaf(2.0f, kdxh, kuh);  // K · x  (exact)
        acc = fmaf(x1, x1, acc);
        acc = fmaf(x2, x2, acc);
        acc = fmaf(0.1f * kx, kx, acc);    // R * u_s^2
        acc = acc + delta;                 // LAM * delta
    }

    // ---- post-tanh: one FMA per state variable ----
    x1 = fmaf(t, g,   bx1);
    x2 = fmaf(t, g,   bx2);
    h1 = fmaf(t, dh1, hm1);
    h2 = fmaf(t, dh2, hm2);
}

__global__ void __launch_bounds__(64, 1) cstr_traj_kernel(
    const float* __restrict__ w,   // (B, 2, T)
    const float* __restrict__ K,   // (1, 2)
    const float* __restrict__ L,   // (4, 4)
    const float* __restrict__ M,   // (1, 4)
    const float* __restrict__ Mo,  // (1, 1)
    float* __restrict__ out)       // (B,)
{
    int b = blockIdx.x * blockDim.x + threadIdx.x;

    const float s = 0.5f;  // sigmoid(phi) = 0.5 + 0.5*tanh(0.5*phi)
    Consts c;
    c.K1 = __ldg(K);  c.K2 = __ldg(K + 1);
    float l[16];
#pragma unroll
    for (int i = 0; i < 16; i++) l[i] = __ldg(L + i);
    c.a11 = s * l[0];           c.a22 = s * l[5];
    c.a33 = s * l[10];          c.a44 = s * l[15];
    c.a12 = s * (l[1] + l[4]);  c.a13 = s * (l[2] + l[8]);
    c.a14 = s * (l[3] + l[12]); c.a23 = s * (l[6] + l[9]);
    c.a24 = s * (l[7] + l[13]); c.a34 = s * (l[11] + l[14]);
    c.bm1 = s * __ldg(M);       c.bm2 = s * __ldg(M + 1);
    c.bm3 = s * __ldg(M + 2);   c.bm4 = s * __ldg(M + 3);
    c.bm0 = s * __ldg(Mo);

    const float4* w0 = (const float4*)(w + (size_t)b * 2 * TSTEPS);
    const float4* w1 = (const float4*)(w + (size_t)b * 2 * TSTEPS + TSTEPS);

    float x1 = 1.0f, x2 = 0.0f, h1 = 1.0f, h2 = 0.0f;

    // Step 0 runs as a NORMAL step (x_hat==x makes delta dynamically inert);
    // only the stage cost differs: reference uses delta=1, normal step adds
    // sigmoid(phi(z0)). Correct once, in closed form from the constants:
    // J0 = 1 - sigmoid(phi(z0)) = 0.5 - 0.5*tanh(phi(z0)/2), z0 = (1,0,1,0).
    float phi0 = ((c.a11 + c.a13) + (c.a33 + c.bm0)) + (c.bm1 + c.bm3);
    float J = 0.5f - 0.5f * tanh_approx(phi0);

    // ---- software prefetch pipeline: PD groups in registers ----
    float4 bA[PD], bB[PD];
#pragma unroll
    for (int d = 0; d < PD; ++d) { bA[d] = w0[d]; bB[d] = w1[d]; }

    // Main loop: groups 0 .. NG-PD-1  (508 groups, multiple of 4 -> static slots)
#pragma unroll 4
    for (int gi = 0; gi < NG - PD; ++gi) {
        int slot = gi & (PD - 1);
        float4 wa = bA[slot], wb = bB[slot];
        bA[slot] = w0[gi + PD];           // prefetch ~16 steps (~800 cyc) ahead
        bB[slot] = w1[gi + PD];
        float acc = 0.0f;
        step<true>(c, wa.x, wb.x, x1, x2, h1, h2, acc);
        step<true>(c, wa.y, wb.y, x1, x2, h1, h2, acc);
        step<true>(c, wa.z, wb.z, x1, x2, h1, h2, acc);
        step<true>(c, wa.w, wb.w, x1, x2, h1, h2, acc);
        J += acc;
    }

    // Peeled tail: groups NG-PD .. NG-1 from the buffers (static slots 0..3)
#pragma unroll
    for (int d = 0; d < PD - 1; ++d) {
        float4 wa = bA[d], wb = bB[d];
        float acc = 0.0f;
        step<true>(c, wa.x, wb.x, x1, x2, h1, h2, acc);
        step<true>(c, wa.y, wb.y, x1, x2, h1, h2, acc);
        step<true>(c, wa.z, wb.z, x1, x2, h1, h2, acc);
        step<true>(c, wa.w, wb.w, x1, x2, h1, h2, acc);
        J += acc;
    }
    {   // last group: final step (i = T-1) updates state, adds no stage cost
        float4 wa = bA[PD - 1], wb = bB[PD - 1];
        float acc = 0.0f;
        step<true >(c, wa.x, wb.x, x1, x2, h1, h2, acc);
        step<true >(c, wa.y, wb.y, x1, x2, h1, h2, acc);
        step<true >(c, wa.z, wb.z, x1, x2, h1, h2, acc);
        step<false>(c, wa.w, wb.w, x1, x2, h1, h2, acc);
        J += acc;
    }

    // Terminal cost: x_T^T (10 I) x_T
    J = fmaf(10.0f * x1, x1, J);
    J = fmaf(10.0f * x2, x2, J);

    if (b < BSIZE) out[b] = J;
}

extern "C" void kernel_launch(void* const* d_in, const int* in_sizes, int n_in,
                              void* d_out, int out_size)
{
    const float* w  = (const float*)d_in[0];
    const float* K  = (const float*)d_in[1];
    const float* L  = (const float*)d_in[2];
    const float* M  = (const float*)d_in[3];
    const float* Mo = (const float*)d_in[4];
    float* out = (float*)d_out;

    // 8192 trajectories, 1 thread each. 128 blocks x 64 threads: one wave,
    // each warp gets a private SMSP (warps 0,1 -> SMSP 0,1 of its SM).
    cstr_traj_kernel<<<BSIZE / 64, 64>>>(w, K, L, M, Mo, out);
}